// round 1
// baseline (speedup 1.0000x reference)
#include <cuda_runtime.h>
#include <cuda_bf16.h>
#include <cstdint>

// Problem: B=2, H=16, S=2048, D=64. fp32 q,k,v,out. attn_bias is per-query
// (broadcast over the key axis) so it cancels exactly in softmax -> ignored.

#define S_LEN 2048
#define DHEAD 64
#define BQ    128   // queries per CTA (= threads per CTA, 1 query/thread)
#define TK    32    // keys per smem tile
#define NTILES (S_LEN / TK)

__device__ __forceinline__ float ex2_approx(float x) {
    float y;
    asm("ex2.approx.f32 %0, %1;" : "=f"(y) : "f"(x));
    return y;
}

__global__ __launch_bounds__(BQ) void sdpa_fp32_kernel(
    const float* __restrict__ qg,
    const float* __restrict__ kg,
    const float* __restrict__ vg,
    float* __restrict__ og)
{
    __shared__ float sK[TK][DHEAD];
    __shared__ float sV[TK][DHEAD];

    const int tid  = threadIdx.x;
    const int bh   = blockIdx.y;                 // 0..31  (B*H)
    const int qidx = blockIdx.x * BQ + tid;      // 0..2047

    const float* qrow  = qg + ((size_t)bh * S_LEN + qidx) * DHEAD;
    const float* kbase = kg + (size_t)bh * S_LEN * DHEAD;
    const float* vbase = vg + (size_t)bh * S_LEN * DHEAD;

    // fold dim_key^-0.5 and log2(e) into q so softmax runs in log2-domain
    const float qscale = 0.125f * 1.4426950408889634f;

    float qreg[DHEAD];
#pragma unroll
    for (int i = 0; i < DHEAD; i += 4) {
        float4 t = *reinterpret_cast<const float4*>(qrow + i);
        qreg[i + 0] = t.x * qscale;
        qreg[i + 1] = t.y * qscale;
        qreg[i + 2] = t.z * qscale;
        qreg[i + 3] = t.w * qscale;
    }

    float acc[DHEAD];
#pragma unroll
    for (int i = 0; i < DHEAD; i++) acc[i] = 0.0f;
    float m = -1e30f;   // running max (log2 domain)
    float l = 0.0f;     // running denominator

    for (int t = 0; t < NTILES; t++) {
        __syncthreads();
        // cooperative tile load: TK*DHEAD floats = 512 float4, 128 threads -> 4 each
        {
            const float4* kgt = reinterpret_cast<const float4*>(kbase + (size_t)t * TK * DHEAD);
            const float4* vgt = reinterpret_cast<const float4*>(vbase + (size_t)t * TK * DHEAD);
            float4* ks = reinterpret_cast<float4*>(&sK[0][0]);
            float4* vs = reinterpret_cast<float4*>(&sV[0][0]);
#pragma unroll
            for (int i = 0; i < (TK * DHEAD / 4); i += BQ) {
                ks[i + tid] = kgt[i + tid];
                vs[i + tid] = vgt[i + tid];
            }
        }
        __syncthreads();

        // scores for this tile (register-resident, 4 partial accumulators for ILP)
        float s[TK];
#pragma unroll
        for (int j = 0; j < TK; j++) {
            const float4* krow = reinterpret_cast<const float4*>(&sK[j][0]);
            float a0 = 0.f, a1 = 0.f, a2 = 0.f, a3 = 0.f;
#pragma unroll
            for (int i = 0; i < DHEAD / 4; i++) {
                float4 kk = krow[i];
                a0 = fmaf(qreg[4 * i + 0], kk.x, a0);
                a1 = fmaf(qreg[4 * i + 1], kk.y, a1);
                a2 = fmaf(qreg[4 * i + 2], kk.z, a2);
                a3 = fmaf(qreg[4 * i + 3], kk.w, a3);
            }
            s[j] = (a0 + a1) + (a2 + a3);
        }

        // online softmax (log2 domain)
        float tmax = s[0];
#pragma unroll
        for (int j = 1; j < TK; j++) tmax = fmaxf(tmax, s[j]);
        float mnew = fmaxf(m, tmax);
        float corr = ex2_approx(m - mnew);
        m = mnew;
        l *= corr;
#pragma unroll
        for (int i = 0; i < DHEAD; i++) acc[i] *= corr;

#pragma unroll
        for (int j = 0; j < TK; j++) {
            float p = ex2_approx(s[j] - m);
            l += p;
            const float4* vrow = reinterpret_cast<const float4*>(&sV[j][0]);
#pragma unroll
            for (int i = 0; i < DHEAD / 4; i++) {
                float4 vv = vrow[i];
                acc[4 * i + 0] = fmaf(p, vv.x, acc[4 * i + 0]);
                acc[4 * i + 1] = fmaf(p, vv.y, acc[4 * i + 1]);
                acc[4 * i + 2] = fmaf(p, vv.z, acc[4 * i + 2]);
                acc[4 * i + 3] = fmaf(p, vv.w, acc[4 * i + 3]);
            }
        }
    }

    const float inv = 1.0f / l;
    float* orow = og + ((size_t)bh * S_LEN + qidx) * DHEAD;
#pragma unroll
    for (int i = 0; i < DHEAD; i += 4) {
        float4 t4 = make_float4(acc[i] * inv, acc[i + 1] * inv,
                                acc[i + 2] * inv, acc[i + 3] * inv);
        *reinterpret_cast<float4*>(orow + i) = t4;
    }
}

extern "C" void kernel_launch(void* const* d_in, const int* in_sizes, int n_in,
                              void* d_out, int out_size) {
    const float* q = (const float*)d_in[0];
    const float* k = (const float*)d_in[1];
    const float* v = (const float*)d_in[2];
    // d_in[3] = attn_bias: per-query constant, cancels in softmax -> unused.
    float* out = (float*)d_out;

    dim3 grid(S_LEN / BQ, 32 /* B*H */);
    sdpa_fp32_kernel<<<grid, BQ>>>(q, k, v, out);
}

// round 2
// speedup vs baseline: 1.2260x; 1.2260x over previous
#include <cuda_runtime.h>
#include <cstdint>

// B=2,H=16,S=2048,D=64 fp32. attn_bias is per-query (cancels in softmax) -> unused.
// Structure: 128 threads/CTA, lane pairs share 2 queries; lane h in {0,1} owns the
// interleaved 16B granules (2i+h) of the d-dimension. K/V tiles double-buffered in
// smem via cp.async. All inner FMAs are fma.rn.f32x2.

#define S_LEN 2048
#define DHEAD 64
#define NTHREADS 128
#define TK 32
#define NT (S_LEN / TK)

typedef unsigned long long u64;

__device__ __forceinline__ u64 fma2(u64 a, u64 b, u64 c) {
    u64 d; asm("fma.rn.f32x2 %0,%1,%2,%3;" : "=l"(d) : "l"(a), "l"(b), "l"(c)); return d;
}
__device__ __forceinline__ u64 add2(u64 a, u64 b) {
    u64 d; asm("add.rn.f32x2 %0,%1,%2;" : "=l"(d) : "l"(a), "l"(b)); return d;
}
__device__ __forceinline__ u64 mul2(u64 a, u64 b) {
    u64 d; asm("mul.rn.f32x2 %0,%1,%2;" : "=l"(d) : "l"(a), "l"(b)); return d;
}
__device__ __forceinline__ u64 pack2(float lo, float hi) {
    u64 d; asm("mov.b64 %0,{%1,%2};" : "=l"(d) : "f"(lo), "f"(hi)); return d;
}
__device__ __forceinline__ float2 unpack2(u64 v) {
    float lo, hi; asm("mov.b64 {%0,%1},%2;" : "=f"(lo), "=f"(hi) : "l"(v));
    return make_float2(lo, hi);
}
__device__ __forceinline__ float ex2(float x) {
    float y; asm("ex2.approx.f32 %0, %1;" : "=f"(y) : "f"(x)); return y;
}
__device__ __forceinline__ void cp16(uint32_t smem, const void* gmem) {
    asm volatile("cp.async.cg.shared.global [%0], [%1], 16;" :: "r"(smem), "l"(gmem));
}
__device__ __forceinline__ void cp_commit() { asm volatile("cp.async.commit_group;"); }
__device__ __forceinline__ void cp_wait1() { asm volatile("cp.async.wait_group 1;"); }
__device__ __forceinline__ void cp_wait0() { asm volatile("cp.async.wait_group 0;"); }

__global__ __launch_bounds__(NTHREADS) void sdpa_f32x2_kernel(
    const float* __restrict__ qg,
    const float* __restrict__ kg,
    const float* __restrict__ vg,
    float* __restrict__ og)
{
    __shared__ float sK[2][TK][DHEAD];
    __shared__ float sV[2][TK][DHEAD];

    const int tid  = threadIdx.x;
    const int h    = tid & 1;        // d-granule parity
    const int pair = tid >> 1;       // 64 pairs
    const int bh   = blockIdx.y;     // 0..31
    const int q0   = blockIdx.x * NTHREADS + pair * 2;

    const float* kbase = kg + (size_t)bh * S_LEN * DHEAD;
    const float* vbase = vg + (size_t)bh * S_LEN * DHEAD;

    const uint32_t skb = (uint32_t)__cvta_generic_to_shared(&sK[0][0][0]);
    const uint32_t svb = (uint32_t)__cvta_generic_to_shared(&sV[0][0][0]);

    // fold 1/sqrt(64) and log2(e): softmax in log2 domain
    const float qsc = 0.125f * 1.4426950408889634f;

    // q fragments: 2 queries x 32 d (granules 2i+h) = 16 u64 each
    u64 q2[2][16];
#pragma unroll
    for (int qi = 0; qi < 2; qi++) {
        const float4* qr = (const float4*)(qg + ((size_t)bh * S_LEN + q0 + qi) * DHEAD);
#pragma unroll
        for (int i = 0; i < 8; i++) {
            float4 t = qr[2 * i + h];
            q2[qi][2 * i + 0] = pack2(t.x * qsc, t.y * qsc);
            q2[qi][2 * i + 1] = pack2(t.z * qsc, t.w * qsc);
        }
    }

    u64 acc[2][16];
#pragma unroll
    for (int qi = 0; qi < 2; qi++)
#pragma unroll
        for (int i = 0; i < 16; i++) acc[qi][i] = 0ull;

    float m0 = -1e30f, m1 = -1e30f, l0 = 0.f, l1 = 0.f;

    // prefetch tile 0 into buffer 0
    {
        const float4* kt = (const float4*)kbase;
        const float4* vt = (const float4*)vbase;
#pragma unroll
        for (int r = 0; r < 4; r++) {
            int idx = r * NTHREADS + tid;
            cp16(skb + idx * 16, kt + idx);
            cp16(svb + idx * 16, vt + idx);
        }
        cp_commit();
    }

    for (int t = 0; t < NT; t++) {
        const int b = t & 1;
        if (t + 1 < NT) {
            const float4* kt = (const float4*)(kbase + (size_t)(t + 1) * TK * DHEAD);
            const float4* vt = (const float4*)(vbase + (size_t)(t + 1) * TK * DHEAD);
            const uint32_t off = (uint32_t)(b ^ 1) * (TK * DHEAD * 4);
#pragma unroll
            for (int r = 0; r < 4; r++) {
                int idx = r * NTHREADS + tid;
                cp16(skb + off + idx * 16, kt + idx);
                cp16(svb + off + idx * 16, vt + idx);
            }
            cp_commit();
            cp_wait1();
        } else {
            cp_wait0();
        }
        __syncthreads();

        // ---- scores for this tile ----
        float s0[TK], s1[TK];
#pragma unroll
        for (int j = 0; j < TK; j++) {
            const char* krow = (const char*)&sK[b][j][0] + h * 16;
            u64 a0 = 0ull, a0b = 0ull, a1 = 0ull, a1b = 0ull;
#pragma unroll
            for (int i = 0; i < 8; i++) {
                ulonglong2 kk = *(const ulonglong2*)(krow + i * 32);
                a0  = fma2(q2[0][2 * i + 0], kk.x, a0);
                a0b = fma2(q2[0][2 * i + 1], kk.y, a0b);
                a1  = fma2(q2[1][2 * i + 0], kk.x, a1);
                a1b = fma2(q2[1][2 * i + 1], kk.y, a1b);
            }
            float2 u0 = unpack2(add2(a0, a0b));
            float sp0 = u0.x + u0.y;
            sp0 += __shfl_xor_sync(0xffffffffu, sp0, 1);
            s0[j] = sp0;
            float2 u1 = unpack2(add2(a1, a1b));
            float sp1 = u1.x + u1.y;
            sp1 += __shfl_xor_sync(0xffffffffu, sp1, 1);
            s1[j] = sp1;
        }

        // ---- online softmax update ----
        float t0 = s0[0], t1 = s1[0];
#pragma unroll
        for (int j = 1; j < TK; j++) { t0 = fmaxf(t0, s0[j]); t1 = fmaxf(t1, s1[j]); }
        bool upd = (t0 > m0) | (t1 > m1);
        if (__ballot_sync(0xffffffffu, upd)) {
            float n0 = fmaxf(m0, t0), n1 = fmaxf(m1, t1);
            float c0 = ex2(m0 - n0),  c1 = ex2(m1 - n1);
            m0 = n0; m1 = n1; l0 *= c0; l1 *= c1;
            u64 cc0 = pack2(c0, c0), cc1 = pack2(c1, c1);
#pragma unroll
            for (int i = 0; i < 16; i++) {
                acc[0][i] = mul2(acc[0][i], cc0);
                acc[1][i] = mul2(acc[1][i], cc1);
            }
        }

        // ---- probabilities + PV ----
#pragma unroll
        for (int j = 0; j < TK; j++) {
            float p0 = ex2(s0[j] - m0); l0 += p0;
            float p1 = ex2(s1[j] - m1); l1 += p1;
            u64 pp0 = pack2(p0, p0), pp1 = pack2(p1, p1);
            const char* vrow = (const char*)&sV[b][j][0] + h * 16;
#pragma unroll
            for (int i = 0; i < 8; i++) {
                ulonglong2 vv = *(const ulonglong2*)(vrow + i * 32);
                acc[0][2 * i + 0] = fma2(pp0, vv.x, acc[0][2 * i + 0]);
                acc[0][2 * i + 1] = fma2(pp0, vv.y, acc[0][2 * i + 1]);
                acc[1][2 * i + 0] = fma2(pp1, vv.x, acc[1][2 * i + 0]);
                acc[1][2 * i + 1] = fma2(pp1, vv.y, acc[1][2 * i + 1]);
            }
        }
        __syncthreads();
    }

    // ---- epilogue ----
    const float inv0 = 1.0f / l0;
    const float inv1 = 1.0f / l1;
    const u64 iv[2] = { pack2(inv0, inv0), pack2(inv1, inv1) };
#pragma unroll
    for (int qi = 0; qi < 2; qi++) {
        char* orow = (char*)(og + ((size_t)bh * S_LEN + q0 + qi) * DHEAD) + h * 16;
#pragma unroll
        for (int i = 0; i < 8; i++) {
            ulonglong2 w;
            w.x = mul2(acc[qi][2 * i + 0], iv[qi]);
            w.y = mul2(acc[qi][2 * i + 1], iv[qi]);
            *(ulonglong2*)(orow + i * 32) = w;
        }
    }
}

extern "C" void kernel_launch(void* const* d_in, const int* in_sizes, int n_in,
                              void* d_out, int out_size) {
    const float* q = (const float*)d_in[0];
    const float* k = (const float*)d_in[1];
    const float* v = (const float*)d_in[2];
    // d_in[3] = attn_bias: row-constant before softmax, cancels exactly -> unused.
    float* out = (float*)d_out;

    dim3 grid(S_LEN / NTHREADS, 32 /* B*H */);
    sdpa_f32x2_kernel<<<grid, NTHREADS>>>(q, k, v, out);
}